// round 15
// baseline (speedup 1.0000x reference)
#include <cuda_runtime.h>
#include <cuda_fp16.h>
#include <mma.h>
#include <cstdint>
#include <cstdio>

using namespace nvcuda;

#define DM   768
#define DI   1536
#define DS   64
#define DTR  48
#define SEQL 2048
#define NB   4            /* effective batch: 2 orig x 2 channel-flip */
#define MTOK (NB*SEQL)    /* 8192 token rows */
#define XPW  176          /* DTR + 2*DS */

/* ---------------- scratch (static device globals; no allocation) -------- */
__device__ float g_act1[2*DM*SEQL];
__device__ float g_h2  [2*SEQL*DM];
__device__ float g_xz  [MTOK*2*DI];
__device__ float g_xmf [NB*DI*SEQL];
__device__ float g_xmb [NB*DI*SEQL];
__device__ float g_xp  [2*MTOK*XPW];        /* xp fp32: dir-f at 0, b at MTOK*XPW */
__device__ float g_dtt [2L*NB*DI*SEQL];     /* dt [dir][b][d][t] */
__device__ float g_yf  [NB*DI*SEQL];
__device__ float g_yb  [NB*DI*SEQL];
__device__ float g_v   [MTOK*DM];
/* fp16 hi/lo operand scratch */
__device__ __half g_Ah [2L*MTOK*DI];        /* A operand (2 dirs for x_proj) */
__device__ __half g_Al [2L*MTOK*DI];
__device__ __half g_Wh [4500000];
__device__ __half g_Wl [4500000];
__device__ __half g_xph[2*MTOK*XPW];
__device__ __half g_xpl[2*MTOK*XPW];

#define OFF_PW  0
#define OFF_IN  (DM*DM)
#define OFF_X   (OFF_IN + 2*DI*DM)
#define OFF_DT  (OFF_X + XPW*DI)
#define OFF_OUT (OFF_DT + DI*DTR)

/* ======================= small helpers ================================= */
__device__ __forceinline__ uint32_t smem_u32(const void* p) {
    uint32_t a;
    asm("{ .reg .u64 t; cvta.to.shared.u64 t, %1; cvt.u32.u64 %0, t; }" : "=r"(a) : "l"(p));
    return a;
}
__device__ __forceinline__ void cpa16(uint32_t dst, const void* src) {
    asm volatile("cp.async.cg.shared.global [%0], [%1], 16;\n" :: "r"(dst), "l"(src));
}
#define CP_COMMIT() asm volatile("cp.async.commit_group;\n" ::: "memory")
#define CP_WAIT(n)  asm volatile("cp.async.wait_group %0;\n" :: "n"(n) : "memory")

/* ---------------- fp32 -> (hi, lo) fp16 split (weights only) ------------ */
__global__ void split_k(const float* __restrict__ in, __half* __restrict__ hi,
                        __half* __restrict__ lo, int n2) {
    int i = blockIdx.x * 256 + threadIdx.x;
    if (i >= n2) return;
    float2 v = ((const float2*)in)[i];
    __half hx = __float2half_rn(v.x), hy = __float2half_rn(v.y);
    ((__half2*)hi)[i] = __halves2half2(hx, hy);
    ((__half2*)lo)[i] = __halves2half2(__float2half_rn(v.x - __half2float(hx)),
                                       __float2half_rn(v.y - __half2float(hy)));
}

/* ================= split-fp16 mma.sync GEMM ============================
   C[m,n] = sum_k A[m,k] * W[n,k],  A = Ah + Al, W = Wh + Wl (fp16 pairs).
   acc += Ah*Wh + Ah*Wl + Al*Wh  -> ~fp32 accuracy.  K-block = 48.        */
#define KBLK 48
#define HST 56                        /* smem row stride, halves (112 B) */
#define TILE_B (128*112)              /* 14336 B per 128xHST half tile */
#define SM_TOTAL (8*TILE_B)           /* 114688 bytes (2 stages x 4 arrays) */

typedef wmma::fragment<wmma::matrix_a,16,16,16,__half,wmma::row_major> HA;
typedef wmma::fragment<wmma::matrix_b,16,16,16,__half,wmma::col_major> HB;

template<int EPI, bool SPLITC, bool TRANSC>
__global__ __launch_bounds__(256, 2) void hmma_gemm_k(
    const __half* __restrict__ Ah_, const __half* __restrict__ Al_,
    const __half* __restrict__ Wh, const __half* __restrict__ Wl,
    float* __restrict__ C_, __half* __restrict__ Ch_, __half* __restrict__ Cl_,
    const float* __restrict__ bias, int M, int N, int K, int lda,
    long aBS, long cBS)
{
    extern __shared__ char smc[];
    float* smf = (float*)smc;
    int tid = threadIdx.x, wid = tid >> 5, lane = tid & 31;
    int m0 = blockIdx.y * 128, n0 = blockIdx.x * 128;
    int wm = (wid & 1) * 64, wn = (wid >> 1) * 32;
    uint32_t sbase = smem_u32(smc);
    const __half* Ah = Ah_ + blockIdx.z * aBS;
    const __half* Al = Al_ + blockIdx.z * aBS;
    float* C = C_ + blockIdx.z * cBS;
    __half* Ch = SPLITC ? Ch_ + blockIdx.z * cBS : nullptr;
    __half* Cl = SPLITC ? Cl_ + blockIdx.z * cBS : nullptr;

    wmma::fragment<wmma::accumulator,16,16,16,float> acc[4][2];
    #pragma unroll
    for (int i = 0; i < 4; i++)
        #pragma unroll
        for (int j = 0; j < 2; j++) wmma::fill_fragment(acc[i][j], 0.f);

    const int NKB = K / KBLK;

    /* 4 arrays x 128 rows x 6 float4-chunks = 3072 float4 per stage */
    auto prefetch = [&](int kb) {
        int k0 = kb * KBLK, s = kb & 1;
        int soff = s * (4 * TILE_B);
        #pragma unroll
        for (int i = 0; i < 12; i++) {
            int e = tid + (i << 8);
            int arr = e / 768, rem = e - arr * 768;
            int r = rem / 6, q = rem - r * 6;
            int off = soff + arr * TILE_B + r * 112 + q * 16;
            const __half* src;
            bool ok = true;
            if (arr < 2) {
                src = (arr == 0 ? Ah : Al) + (long)(m0 + r) * lda + k0 + q * 8;
            } else {
                src = (arr == 2 ? Wh : Wl) + (long)(n0 + r) * K + k0 + q * 8;
                ok = (n0 + r < N);
            }
            if (ok) cpa16(sbase + off, src);
            else    *(float4*)(smc + off) = make_float4(0.f, 0.f, 0.f, 0.f);
        }
        CP_COMMIT();
    };

    prefetch(0);
    for (int kb = 0; kb < NKB; kb++) {
        int s = kb & 1;
        CP_WAIT(0);
        __syncthreads();
        if (kb + 1 < NKB) prefetch(kb + 1);
        const char* st = smc + s * (4 * TILE_B);
        const __half* pAh = (const __half*)(st);
        const __half* pAl = (const __half*)(st + TILE_B);
        const __half* pBh = (const __half*)(st + 2*TILE_B);
        const __half* pBl = (const __half*)(st + 3*TILE_B);
        #pragma unroll
        for (int ks = 0; ks < 3; ks++) {
            HB bh[2], bl[2];
            #pragma unroll
            for (int j = 0; j < 2; j++) {
                wmma::load_matrix_sync(bh[j], pBh + (wn + j*16) * HST + ks*16, HST);
                wmma::load_matrix_sync(bl[j], pBl + (wn + j*16) * HST + ks*16, HST);
            }
            #pragma unroll
            for (int i = 0; i < 4; i++) {
                HA ah, al;
                wmma::load_matrix_sync(ah, pAh + (wm + i*16) * HST + ks*16, HST);
                wmma::load_matrix_sync(al, pAl + (wm + i*16) * HST + ks*16, HST);
                wmma::mma_sync(acc[i][0], ah, bh[0], acc[i][0]);
                wmma::mma_sync(acc[i][1], ah, bh[1], acc[i][1]);
                wmma::mma_sync(acc[i][0], ah, bl[0], acc[i][0]);
                wmma::mma_sync(acc[i][1], ah, bl[1], acc[i][1]);
                wmma::mma_sync(acc[i][0], al, bh[0], acc[i][0]);
                wmma::mma_sync(acc[i][1], al, bh[1], acc[i][1]);
            }
        }
    }
    __syncthreads();

    /* stage C through shared */
    constexpr int STGX = TRANSC ? 133 : 132;
    #pragma unroll
    for (int i = 0; i < 4; i++)
        #pragma unroll
        for (int j = 0; j < 2; j++)
            wmma::store_matrix_sync(smf + (wm + i*16) * STGX + wn + j*16,
                                    acc[i][j], STGX, wmma::mem_row_major);
    __syncthreads();

    if (TRANSC) {
        /* transposed output: out[(b*N + n)*SEQL + t],  m = b*SEQL + t */
        #pragma unroll
        for (int it = 0; it < 16; it++) {
            int col = it * 8 + wid;
            int n = n0 + col;
            #pragma unroll
            for (int rr = 0; rr < 4; rr++) {
                int r = rr * 32 + lane;
                float v = smf[r * 133 + col];
                if (EPI == 2) {
                    v += bias[n];
                    v = (v > 20.f) ? v : log1pf(__expf(v));
                }
                int m = m0 + r;
                int b = m >> 11, t = m & 2047;
                C[((long)(b * N + n)) * SEQL + t] = v;
            }
        }
        return;
    }

    #pragma unroll
    for (int it = 0; it < 16; it++) {
        int e = tid + (it << 8);
        int r = e >> 5, c4 = (e & 31) << 2;
        int n = n0 + c4;
        if (n < N) {
            float4 v = *(float4*)(smf + r * 132 + c4);
            if (EPI == 1) {
                v.x = v.x > 0.f ? v.x : 0.01f * v.x;
                v.y = v.y > 0.f ? v.y : 0.01f * v.y;
                v.z = v.z > 0.f ? v.z : 0.01f * v.z;
                v.w = v.w > 0.f ? v.w : 0.01f * v.w;
            } else if (EPI == 2) {
                v.x += bias[n];     v.y += bias[n + 1];
                v.z += bias[n + 2]; v.w += bias[n + 3];
                v.x = (v.x > 20.f) ? v.x : log1pf(__expf(v.x));
                v.y = (v.y > 20.f) ? v.y : log1pf(__expf(v.y));
                v.z = (v.z > 20.f) ? v.z : log1pf(__expf(v.z));
                v.w = (v.w > 20.f) ? v.w : log1pf(__expf(v.w));
            }
            long off = (long)(m0 + r) * N + n;
            *(float4*)(C + off) = v;
            if (SPLITC) {
                __half hx = __float2half_rn(v.x), hy = __float2half_rn(v.y);
                __half hz = __float2half_rn(v.z), hw = __float2half_rn(v.w);
                *(__half2*)(Ch + off)     = __halves2half2(hx, hy);
                *(__half2*)(Ch + off + 2) = __halves2half2(hz, hw);
                *(__half2*)(Cl + off)     = __halves2half2(
                    __float2half_rn(v.x - __half2float(hx)),
                    __float2half_rn(v.y - __half2float(hy)));
                *(__half2*)(Cl + off + 2) = __halves2half2(
                    __float2half_rn(v.z - __half2float(hz)),
                    __float2half_rn(v.w - __half2float(hw)));
            }
        }
    }
}

/* ---------------- 1. BatchNorm3d(eval) + LeakyReLU ---------------------- */
__global__ void bn_lrelu_k(const float* __restrict__ x, const float* __restrict__ g,
                           const float* __restrict__ be, const float* __restrict__ mu,
                           const float* __restrict__ var) {
    int i = blockIdx.x * 256 + threadIdx.x;
    if (i >= 2*DM*SEQL) return;
    int c = (i / SEQL) % DM;
    float v = (x[i] - mu[c]) * rsqrtf(var[c] + 1e-5f) * g[c] + be[c];
    g_act1[i] = v > 0.f ? v : 0.01f * v;
}

/* ------- 2. depthwise conv3d 3x3x3 SAME, fused transpose+split ---------- */
__global__ void dwconv_t(const float* __restrict__ wt) {
    __shared__ float s[32][33];
    int b = blockIdx.z, c0 = blockIdx.y * 32, t0 = blockIdx.x * 32;
    int tx = threadIdx.x, ty = threadIdx.y;     /* 32 x 8 */
    #pragma unroll
    for (int i = 0; i < 4; i++) {
        int c = c0 + ty + i*8;
        int t = t0 + tx;
        int w = t & 15, h = (t >> 4) & 15, d = t >> 8;
        const float* wp = wt + c * 27;
        const float* ip = g_act1 + (size_t)(b*DM + c) * SEQL;
        float acc = 0.f;
        #pragma unroll
        for (int kd = 0; kd < 3; kd++) {
            int dd = d + kd - 1; if (dd < 0 || dd > 7) continue;
            #pragma unroll
            for (int kh = 0; kh < 3; kh++) {
                int hh = h + kh - 1; if (hh < 0 || hh > 15) continue;
                #pragma unroll
                for (int kw = 0; kw < 3; kw++) {
                    int ww = w + kw - 1; if (ww < 0 || ww > 15) continue;
                    acc += wp[kd*9 + kh*3 + kw] * ip[dd*256 + hh*16 + ww];
                }
            }
        }
        s[ty + i*8][tx] = acc;
    }
    __syncthreads();
    #pragma unroll
    for (int i = 0; i < 4; i++) {
        int t = t0 + ty + i*8;
        int c = c0 + tx;
        float v = s[tx][ty + i*8];
        __half hv = __float2half_rn(v);
        long o = ((long)(b * SEQL + t)) * DM + c;
        g_Ah[o] = hv;
        g_Al[o] = __float2half_rn(v - __half2float(hv));
    }
}

/* -------- 32x32 transpose, fp32 in -> fp16 hi/lo out, dual-source ------- */
__global__ void transpose_h(const float* __restrict__ inf, const float* __restrict__ inb,
                            __half* __restrict__ hi, __half* __restrict__ lo,
                            int R, int Cc, int nb, long outBS) {
    __shared__ float s[32][33];
    int z = blockIdx.z;
    int dirb = z / nb, b = z - dirb * nb;
    const float* in = dirb ? inb : inf;
    hi += dirb * outBS; lo += dirb * outBS;
    int r0 = blockIdx.y * 32, c0 = blockIdx.x * 32;
    int tx = threadIdx.x, ty = threadIdx.y;     /* 32 x 8 */
    #pragma unroll
    for (int i = 0; i < 4; i++)
        s[ty + i*8][tx] = in[((long)(b * R + r0 + ty + i*8)) * Cc + c0 + tx];
    __syncthreads();
    #pragma unroll
    for (int i = 0; i < 4; i++) {
        float v = s[tx][ty + i*8];
        __half hv = __float2half_rn(v);
        long o = ((long)(b * Cc + c0 + ty + i*8)) * R + r0 + tx;
        hi[o] = hv;
        lo[o] = __float2half_rn(v - __half2float(hv));
    }
}

/* ---------------- 4. LayerNorm; emit X2 halves (orig + c-flip) ---------- */
__global__ void ln_k(const float* __restrict__ gam, const float* __restrict__ bet) {
    int m = blockIdx.x;
    __shared__ float red[16];
    const float* row = g_h2 + (size_t)m * DM;
    float s = 0.f, s2 = 0.f;
    for (int c = threadIdx.x; c < DM; c += 256) { float v = row[c]; s += v; s2 += v*v; }
    #pragma unroll
    for (int o = 16; o; o >>= 1) {
        s  += __shfl_xor_sync(~0u, s, o);
        s2 += __shfl_xor_sync(~0u, s2, o);
    }
    int wid = threadIdx.x >> 5, ln = threadIdx.x & 31;
    if (ln == 0) { red[wid] = s; red[8 + wid] = s2; }
    __syncthreads();
    float ts = 0.f, ts2 = 0.f;
    #pragma unroll
    for (int i = 0; i < 8; i++) { ts += red[i]; ts2 += red[8 + i]; }
    float mu = ts / 768.f;
    float var = ts2 / 768.f - mu * mu;
    float rs = rsqrtf(var + 1e-5f);
    for (int c = threadIdx.x; c < DM; c += 256) {
        float v = (row[c] - mu) * rs * gam[c] + bet[c];
        __half hv = __float2half_rn(v);
        __half lv = __float2half_rn(v - __half2float(hv));
        size_t o0 = (size_t)m * DM + c;
        size_t o1 = (size_t)(4096 + m) * DM + (DM - 1 - c);
        g_Ah[o0] = hv; g_Al[o0] = lv;
        g_Ah[o1] = hv; g_Al[o1] = lv;
    }
}

/* ---------------- 6. causal + anti-causal depthwise conv1d + SiLU ------- */
__global__ __launch_bounds__(256) void conv1d_k(const float* __restrict__ cw,
                                                const float* __restrict__ cb) {
    __shared__ float s[32][71];
    __shared__ float sw[32][4];
    __shared__ float sb[32];
    int b = blockIdx.z, d0 = blockIdx.y * 32, t0 = blockIdx.x * 64;
    int tid = threadIdx.x;
    if (tid < 128) sw[tid >> 2][tid & 3] = cw[(d0 + (tid >> 2)) * 4 + (tid & 3)];
    if (tid < 32)  sb[tid] = cb[d0 + tid];
    for (int e = tid; e < 32 * 70; e += 256) {
        int dd = e & 31, tt = e >> 5;
        int t = t0 - 3 + tt;
        float v = 0.f;
        if (t >= 0 && t < SEQL) v = g_xz[((size_t)(b * SEQL + t)) * (2*DI) + d0 + dd];
        s[dd][tt] = v;
    }
    __syncthreads();
    int tt = tid & 63, dg = tid >> 6;
    for (int dl = dg; dl < 32; dl += 4) {
        float w0 = sw[dl][0], w1 = sw[dl][1], w2 = sw[dl][2], w3 = sw[dl][3], bb = sb[dl];
        float f = w0*s[dl][tt]   + w1*s[dl][tt+1] + w2*s[dl][tt+2] + w3*s[dl][tt+3] + bb;
        float g = w0*s[dl][tt+6] + w1*s[dl][tt+5] + w2*s[dl][tt+4] + w3*s[dl][tt+3] + bb;
        size_t o = ((size_t)(b * DI + d0 + dl)) * SEQL + t0 + tt;
        g_xmf[o] = f / (1.f + __expf(-f));
        g_xmb[o] = g / (1.f + __expf(-g));
    }
}

/* ---------------- 10. selective scan (fwd + bwd) ------------------------
   Dynamic smem (53248 B): shbc 16384 | shred 32768 | sparam 4096.
   Per-32-step staging of {dt, dt*x, q=ex2(dt*delta)}; inner loop does one
   broadcast LDS.128 and ONE ex2 per step (e2 = e1*q; A2-A1 lane-uniform,
   read from the data).                                                    */
#define SCAN_SMEM (16384 + 32768 + 4096)
__global__ __launch_bounds__(256) void scan_k(const float* __restrict__ A_log) {
    extern __shared__ char ssm[];
    float4* shbc   = (float4*)ssm;                     /* [32][32] f4 = 16384 B */
    float*  shred  = (float*)(ssm + 16384);            /* [8][32][32] f = 32768 B */
    float4* sparam = (float4*)(ssm + 16384 + 32768);   /* [8][32] f4 = 4096 B */
    int dir = blockIdx.z, b = blockIdx.y;
    int wid = threadIdx.x >> 5, lane = threadIdx.x & 31;
    int d = blockIdx.x * 8 + wid;
    const float* dt = g_dtt + (size_t)dir*NB*DI*SEQL + ((size_t)(b*DI + d)) * SEQL;
    const float* xm = (dir ? g_xmb : g_xmf) + ((size_t)(b*DI + d)) * SEQL;
    const float* xp = g_xp + (size_t)dir*MTOK*XPW + (size_t)b * SEQL * XPW;
    float* y = (dir ? g_yb : g_yf) + ((size_t)(b*DI + d)) * SEQL;
    const float L2E = 1.4426950408889634f;
    float A1 = -__expf(A_log[d*DS + lane])       * L2E;
    float A2 = -__expf(A_log[d*DS + 32 + lane])  * L2E;
    float delta0 = __shfl_sync(~0u, A2 - A1, 0);
    float h1 = 0.f, h2 = 0.f;
    float* myred = shred + wid * 1024;
    for (int s0 = 0; s0 < SEQL; s0 += 32) {
        __syncthreads();
        for (int e = threadIdx.x; e < 1024; e += 256) {
            int r = e >> 5, n = e & 31;
            int t = dir ? (SEQL - 1 - (s0 + r)) : (s0 + r);
            const float* p = xp + (size_t)t * XPW;
            shbc[r * 32 + n] = make_float4(p[48 + n], p[80 + n], p[112 + n], p[144 + n]);
        }
        int tl = dir ? (SEQL - 1 - (s0 + lane)) : (s0 + lane);
        float dtv_b = dt[tl];
        float ux_b  = dtv_b * xm[tl];
        float q32_b;
        asm("ex2.approx.f32 %0, %1;" : "=f"(q32_b) : "f"(dtv_b * delta0));
        sparam[wid * 32 + lane] = make_float4(dtv_b, ux_b, q32_b, 0.f);
        __syncthreads();
        #pragma unroll
        for (int j = 0; j < 32; j++) {
            float4 p  = sparam[wid * 32 + j];     /* uniform addr: broadcast */
            float4 bc = shbc[j * 32 + lane];
            float e1;
            asm("ex2.approx.f32 %0, %1;" : "=f"(e1) : "f"(p.x * A1));
            float e2 = e1 * p.z;
            h1 = e1 * h1 + p.y * bc.x;
            h2 = e2 * h2 + p.y * bc.y;
            myred[j * 32 + (lane ^ j)] = h1 * bc.z + h2 * bc.w;
        }
        __syncwarp();
        float sum = 0.f;
        #pragma unroll
        for (int i = 0; i < 32; i++) sum += myred[lane * 32 + (i ^ lane)];
        y[dir ? (SEQL - 1 - s0 - lane) : (s0 + lane)] = sum;
    }
}

/* ---------------- 11. combine + gate -> u halves (token-major) ---------- */
__global__ void combine_k(const float* __restrict__ Dskip) {
    __shared__ float s[32][33];
    int b = blockIdx.z, d0 = blockIdx.y * 32, t0 = blockIdx.x * 32;
    int tx = threadIdx.x, ty = threadIdx.y;     /* 32 x 8 */
    #pragma unroll
    for (int i = 0; i < 4; i++) {
        int d = d0 + ty + i*8;
        size_t I = ((size_t)(b * DI + d)) * SEQL + t0 + tx;
        float v = g_yf[I] + g_yb[I] + Dskip[d] * (g_xmf[I] + g_xmb[I]);
        s[ty + i*8][tx] = v;
    }
    __syncthreads();
    #pragma unroll
    for (int i = 0; i < 4; i++) {
        int t = t0 + ty + i*8;
        int d = d0 + tx;
        float z = g_xz[((size_t)(b * SEQL + t)) * (2*DI) + DI + d];
        float sz = z / (1.f + __expf(-z));
        float u = s[tx][ty + i*8] * sz;
        __half hu = __float2half_rn(u);
        size_t o = ((size_t)(b * SEQL + t)) * DI + d;
        g_Ah[o] = hu;
        g_Al[o] = __float2half_rn(u - __half2float(hu));
    }
}

/* ---------------- 13. final: average 4 directions ----------------------- */
__global__ void final_k(float* __restrict__ out) {
    int i = blockIdx.x * 256 + threadIdx.x;
    if (i >= 2 * SEQL * DM) return;
    int c = i % DM;
    size_t ml = (size_t)(i / DM);
    out[i] = 0.25f * (g_v[ml * DM + c] +
                      g_v[(ml + (size_t)2 * SEQL) * DM + (DM - 1 - c)]);
}

/* ------------------------------------------------------------------------ */
static inline void split_w(const float* p, __half* h, __half* l, long n) {
    int n2 = (int)(n / 2);
    split_k<<<(n2 + 255) / 256, 256>>>(p, h, l, n2);
}

extern "C" void kernel_launch(void* const* d_in, const int* in_sizes, int n_in,
                              void* d_out, int out_size) {
    const float* x        = (const float*)d_in[0];
    const float* bn_gamma = (const float*)d_in[1];
    const float* bn_beta  = (const float*)d_in[2];
    const float* bn_mean  = (const float*)d_in[3];
    const float* bn_var   = (const float*)d_in[4];
    const float* dw_w     = (const float*)d_in[5];
    const float* pw_w     = (const float*)d_in[6];
    const float* ln_gamma = (const float*)d_in[7];
    const float* ln_beta  = (const float*)d_in[8];
    const float* W_in     = (const float*)d_in[9];
    const float* conv_w   = (const float*)d_in[10];
    const float* conv_b   = (const float*)d_in[11];
    const float* W_x      = (const float*)d_in[12];
    const float* W_dt     = (const float*)d_in[13];
    const float* b_dt     = (const float*)d_in[14];
    const float* A_log    = (const float*)d_in[15];
    const float* D_skip   = (const float*)d_in[16];
    const float* W_out    = (const float*)d_in[17];
    float* out            = (float*)d_out;

    float *p_h2, *p_xz, *p_xmf, *p_xmb, *p_xp, *p_dtt, *p_v;
    __half *p_Ah, *p_Al, *p_Wh, *p_Wl, *p_xph, *p_xpl;
    cudaGetSymbolAddress((void**)&p_h2,   g_h2);
    cudaGetSymbolAddress((void**)&p_xz,   g_xz);
    cudaGetSymbolAddress((void**)&p_xmf,  g_xmf);
    cudaGetSymbolAddress((void**)&p_xmb,  g_xmb);
    cudaGetSymbolAddress((void**)&p_xp,   g_xp);
    cudaGetSymbolAddress((void**)&p_dtt,  g_dtt);
    cudaGetSymbolAddress((void**)&p_v,    g_v);
    cudaGetSymbolAddress((void**)&p_Ah,   g_Ah);
    cudaGetSymbolAddress((void**)&p_Al,   g_Al);
    cudaGetSymbolAddress((void**)&p_Wh,   g_Wh);
    cudaGetSymbolAddress((void**)&p_Wl,   g_Wl);
    cudaGetSymbolAddress((void**)&p_xph,  g_xph);
    cudaGetSymbolAddress((void**)&p_xpl,  g_xpl);

    cudaFuncSetAttribute(hmma_gemm_k<0,false,false>, cudaFuncAttributeMaxDynamicSharedMemorySize, SM_TOTAL);
    cudaFuncSetAttribute(hmma_gemm_k<0,true,false>,  cudaFuncAttributeMaxDynamicSharedMemorySize, SM_TOTAL);
    cudaFuncSetAttribute(hmma_gemm_k<1,false,false>, cudaFuncAttributeMaxDynamicSharedMemorySize, SM_TOTAL);
    cudaFuncSetAttribute(hmma_gemm_k<2,false,true>,  cudaFuncAttributeMaxDynamicSharedMemorySize, SM_TOTAL);
    cudaFuncSetAttribute(scan_k, cudaFuncAttributeMaxDynamicSharedMemorySize, SCAN_SMEM);

    /* [0] bn, [1] split pw, [2] fused dwconv+transpose+split, [3] pw GEMM */
    bn_lrelu_k<<<12288, 256>>>(x, bn_gamma, bn_beta, bn_mean, bn_var);
    split_w(pw_w, p_Wh + OFF_PW, p_Wl + OFF_PW, (long)DM*DM);
    dwconv_t<<<dim3(64, 24, 2), dim3(32, 8)>>>(dw_w);
    hmma_gemm_k<1,false,false><<<dim3(6, 32, 1), 256, SM_TOTAL>>>(
        p_Ah, p_Al, p_Wh + OFF_PW, p_Wl + OFF_PW, p_h2, nullptr, nullptr,
        nullptr, 4096, DM, DM, DM, 0L, 0L);
    /* layernorm -> X2 halves */
    ln_k<<<2*SEQL, 256>>>(ln_gamma, ln_beta);
    split_w(W_in, p_Wh + OFF_IN, p_Wl + OFF_IN, (long)2*DI*DM);
    /* in_proj: [8192,768] x [3072,768]^T */
    hmma_gemm_k<0,false,false><<<dim3(24, 64, 1), 256, SM_TOTAL>>>(
        p_Ah, p_Al, p_Wh + OFF_IN, p_Wl + OFF_IN, p_xz, nullptr, nullptr,
        nullptr, MTOK, 2*DI, DM, DM, 0L, 0L);
    /* remaining weight splits */
    split_w(W_x,   p_Wh + OFF_X,   p_Wl + OFF_X,   (long)XPW*DI);
    split_w(W_dt,  p_Wh + OFF_DT,  p_Wl + OFF_DT,  (long)DI*DTR);
    split_w(W_out, p_Wh + OFF_OUT, p_Wl + OFF_OUT, (long)DM*DI);
    /* dual-direction conv1d + SiLU -> xm [b,d,t] */
    conv1d_k<<<dim3(32, 48, NB), 256>>>(conv_w, conv_b);
    /* xm (both dirs) -> token-major halves */
    transpose_h<<<dim3(64, 48, 8), dim3(32, 8)>>>(p_xmf, p_xmb, p_Ah, p_Al,
                                                  DI, SEQL, NB, (long)MTOK*DI);
    /* x_proj both dirs: [8192,1536] x [176,1536]^T (emits fp32 + halves) */
    hmma_gemm_k<0,true,false><<<dim3(2, 64, 2), 256, SM_TOTAL>>>(
        p_Ah, p_Al, p_Wh + OFF_X, p_Wl + OFF_X, p_xp, p_xph, p_xpl,
        nullptr, MTOK, XPW, DI, DI, (long)MTOK*DI, (long)MTOK*XPW);
    /* dt proj + softplus, transposed epilogue -> dtt [dir][b][d][t] */
    hmma_gemm_k<2,false,true><<<dim3(12, 64, 2), 256, SM_TOTAL>>>(
        p_xph, p_xpl, p_Wh + OFF_DT, p_Wl + OFF_DT, p_dtt, nullptr, nullptr,
        b_dt, MTOK, DI, DTR, XPW, (long)MTOK*XPW, (long)NB*DI*SEQL);
    /* selective scan */
    scan_k<<<dim3(DI/8, NB, 2), 256, SCAN_SMEM>>>(A_log);
    /* combine + gate -> u halves */
    combine_k<<<dim3(64, 48, NB), dim3(32, 8)>>>(D_skip);
    /* out_proj: [8192,1536] x [768,1536]^T */
    hmma_gemm_k<0,false,false><<<dim3(6, 64, 1), 256, SM_TOTAL>>>(
        p_Ah, p_Al, p_Wh + OFF_OUT, p_Wl + OFF_OUT, p_v, nullptr, nullptr,
        nullptr, MTOK, DM, DI, DI, 0L, 0L);
    final_k<<<12288, 256>>>(out);
    (void)in_sizes; (void)n_in; (void)out_size;
}

// round 16
// speedup vs baseline: 1.0645x; 1.0645x over previous
#include <cuda_runtime.h>
#include <cuda_fp16.h>
#include <mma.h>
#include <cstdint>
#include <cstdio>

using namespace nvcuda;

#define DM   768
#define DI   1536
#define DS   64
#define DTR  48
#define SEQL 2048
#define NB   4            /* effective batch: 2 orig x 2 channel-flip */
#define MTOK (NB*SEQL)    /* 8192 token rows */
#define XPW  176          /* DTR + 2*DS */

/* ---------------- scratch (static device globals; no allocation) -------- */
__device__ float g_act1[2*DM*SEQL];
__device__ float g_h2  [2*SEQL*DM];
__device__ float g_xz  [MTOK*2*DI];
__device__ float g_xmf [NB*DI*SEQL];
__device__ float g_xmb [NB*DI*SEQL];
__device__ float g_xp  [2*MTOK*XPW];        /* xp fp32: dir-f at 0, b at MTOK*XPW */
__device__ float g_dtt [2L*NB*DI*SEQL];     /* dt [dir][b][d][t] */
__device__ float g_yf  [NB*DI*SEQL];
__device__ float g_yb  [NB*DI*SEQL];
__device__ float g_v   [MTOK*DM];
/* fp16 hi/lo operand scratch */
__device__ __half g_Ah [2L*MTOK*DI];        /* A operand (2 dirs for x_proj) */
__device__ __half g_Al [2L*MTOK*DI];
__device__ __half g_Wh [4500000];
__device__ __half g_Wl [4500000];
__device__ __half g_xph[2*MTOK*XPW];
__device__ __half g_xpl[2*MTOK*XPW];

#define OFF_PW  0
#define OFF_IN  (DM*DM)
#define OFF_X   (OFF_IN + 2*DI*DM)
#define OFF_DT  (OFF_X + XPW*DI)
#define OFF_OUT (OFF_DT + DI*DTR)

/* segment sizes in float2 units */
#define S_PW  (DM*DM/2)             /* 294912 */
#define S_IN  (2*DI*DM/2)           /* 1179648 */
#define S_X   (XPW*DI/2)            /* 135168 */
#define S_DT  (DI*DTR/2)            /* 36864 */
#define S_OUT (DM*DI/2)             /* 589824 */
#define S_TOT (S_PW+S_IN+S_X+S_DT+S_OUT)

/* ======================= small helpers ================================= */
__device__ __forceinline__ uint32_t smem_u32(const void* p) {
    uint32_t a;
    asm("{ .reg .u64 t; cvta.to.shared.u64 t, %1; cvt.u32.u64 %0, t; }" : "=r"(a) : "l"(p));
    return a;
}
__device__ __forceinline__ void cpa16(uint32_t dst, const void* src) {
    asm volatile("cp.async.cg.shared.global [%0], [%1], 16;\n" :: "r"(dst), "l"(src));
}
#define CP_COMMIT() asm volatile("cp.async.commit_group;\n" ::: "memory")
#define CP_WAIT(n)  asm volatile("cp.async.wait_group %0;\n" :: "n"(n) : "memory")

/* -------- fp32 -> (hi, lo) fp16 split: all 5 weights, one launch -------- */
__global__ void split_all_k(const float* __restrict__ pw, const float* __restrict__ win,
                            const float* __restrict__ wx, const float* __restrict__ wdt,
                            const float* __restrict__ wout) {
    int i = blockIdx.x * 256 + threadIdx.x;
    if (i >= S_TOT) return;
    const float* src; long dst;
    if (i < S_PW)                      { src = pw;   dst = OFF_PW/2  + i; }
    else if (i < S_PW+S_IN)            { src = win;  dst = OFF_IN/2  + (i - S_PW); i -= S_PW; }
    else if (i < S_PW+S_IN+S_X)        { src = wx;   dst = OFF_X/2   + (i - S_PW - S_IN); i -= S_PW+S_IN; }
    else if (i < S_PW+S_IN+S_X+S_DT)   { src = wdt;  dst = OFF_DT/2  + (i - S_PW - S_IN - S_X); i -= S_PW+S_IN+S_X; }
    else                               { src = wout; dst = OFF_OUT/2 + (i - S_PW - S_IN - S_X - S_DT); i -= S_PW+S_IN+S_X+S_DT; }
    float2 v = ((const float2*)src)[i];
    __half hx = __float2half_rn(v.x), hy = __float2half_rn(v.y);
    ((__half2*)g_Wh)[dst] = __halves2half2(hx, hy);
    ((__half2*)g_Wl)[dst] = __halves2half2(__float2half_rn(v.x - __half2float(hx)),
                                           __float2half_rn(v.y - __half2float(hy)));
}

/* ================= split-fp16 mma.sync GEMM ============================
   C[m,n] = sum_k A[m,k] * W[n,k],  A = Ah + Al, W = Wh + Wl (fp16 pairs).
   acc += Ah*Wh + Ah*Wl + Al*Wh  -> ~fp32 accuracy.  K-block = 48.        */
#define KBLK 48
#define HST 56                        /* smem row stride, halves (112 B) */
#define TILE_B (128*112)              /* 14336 B per 128xHST half tile */
#define SM_TOTAL (8*TILE_B)           /* 114688 bytes (2 stages x 4 arrays) */

typedef wmma::fragment<wmma::matrix_a,16,16,16,__half,wmma::row_major> HA;
typedef wmma::fragment<wmma::matrix_b,16,16,16,__half,wmma::col_major> HB;

template<int EPI, bool SPLITC, bool TRANSC>
__global__ __launch_bounds__(256, 2) void hmma_gemm_k(
    const __half* __restrict__ Ah_, const __half* __restrict__ Al_,
    const __half* __restrict__ Wh, const __half* __restrict__ Wl,
    float* __restrict__ C_, __half* __restrict__ Ch_, __half* __restrict__ Cl_,
    const float* __restrict__ bias, int M, int N, int K, int lda,
    long aBS, long cBS)
{
    extern __shared__ char smc[];
    float* smf = (float*)smc;
    int tid = threadIdx.x, wid = tid >> 5, lane = tid & 31;
    int m0 = blockIdx.y * 128, n0 = blockIdx.x * 128;
    int wm = (wid & 1) * 64, wn = (wid >> 1) * 32;
    uint32_t sbase = smem_u32(smc);
    const __half* Ah = Ah_ + blockIdx.z * aBS;
    const __half* Al = Al_ + blockIdx.z * aBS;
    float* C = C_ + blockIdx.z * cBS;
    __half* Ch = SPLITC ? Ch_ + blockIdx.z * cBS : nullptr;
    __half* Cl = SPLITC ? Cl_ + blockIdx.z * cBS : nullptr;

    wmma::fragment<wmma::accumulator,16,16,16,float> acc[4][2];
    #pragma unroll
    for (int i = 0; i < 4; i++)
        #pragma unroll
        for (int j = 0; j < 2; j++) wmma::fill_fragment(acc[i][j], 0.f);

    const int NKB = K / KBLK;

    /* 4 arrays x 128 rows x 6 float4-chunks = 3072 float4 per stage */
    auto prefetch = [&](int kb) {
        int k0 = kb * KBLK, s = kb & 1;
        int soff = s * (4 * TILE_B);
        #pragma unroll
        for (int i = 0; i < 12; i++) {
            int e = tid + (i << 8);
            int arr = e / 768, rem = e - arr * 768;
            int r = rem / 6, q = rem - r * 6;
            int off = soff + arr * TILE_B + r * 112 + q * 16;
            const __half* src;
            bool ok = true;
            if (arr < 2) {
                src = (arr == 0 ? Ah : Al) + (long)(m0 + r) * lda + k0 + q * 8;
            } else {
                src = (arr == 2 ? Wh : Wl) + (long)(n0 + r) * K + k0 + q * 8;
                ok = (n0 + r < N);
            }
            if (ok) cpa16(sbase + off, src);
            else    *(float4*)(smc + off) = make_float4(0.f, 0.f, 0.f, 0.f);
        }
        CP_COMMIT();
    };

    prefetch(0);
    for (int kb = 0; kb < NKB; kb++) {
        int s = kb & 1;
        CP_WAIT(0);
        __syncthreads();
        if (kb + 1 < NKB) prefetch(kb + 1);
        const char* st = smc + s * (4 * TILE_B);
        const __half* pAh = (const __half*)(st);
        const __half* pAl = (const __half*)(st + TILE_B);
        const __half* pBh = (const __half*)(st + 2*TILE_B);
        const __half* pBl = (const __half*)(st + 3*TILE_B);
        #pragma unroll
        for (int ks = 0; ks < 3; ks++) {
            HB bh[2], bl[2];
            #pragma unroll
            for (int j = 0; j < 2; j++) {
                wmma::load_matrix_sync(bh[j], pBh + (wn + j*16) * HST + ks*16, HST);
                wmma::load_matrix_sync(bl[j], pBl + (wn + j*16) * HST + ks*16, HST);
            }
            #pragma unroll
            for (int i = 0; i < 4; i++) {
                HA ah, al;
                wmma::load_matrix_sync(ah, pAh + (wm + i*16) * HST + ks*16, HST);
                wmma::load_matrix_sync(al, pAl + (wm + i*16) * HST + ks*16, HST);
                wmma::mma_sync(acc[i][0], ah, bh[0], acc[i][0]);
                wmma::mma_sync(acc[i][1], ah, bh[1], acc[i][1]);
                wmma::mma_sync(acc[i][0], ah, bl[0], acc[i][0]);
                wmma::mma_sync(acc[i][1], ah, bl[1], acc[i][1]);
                wmma::mma_sync(acc[i][0], al, bh[0], acc[i][0]);
                wmma::mma_sync(acc[i][1], al, bh[1], acc[i][1]);
            }
        }
    }
    __syncthreads();

    /* stage C through shared */
    constexpr int STGX = TRANSC ? 133 : 132;
    #pragma unroll
    for (int i = 0; i < 4; i++)
        #pragma unroll
        for (int j = 0; j < 2; j++)
            wmma::store_matrix_sync(smf + (wm + i*16) * STGX + wn + j*16,
                                    acc[i][j], STGX, wmma::mem_row_major);
    __syncthreads();

    if (TRANSC) {
        /* transposed output: out[(b*N + n)*SEQL + t],  m = b*SEQL + t */
        #pragma unroll
        for (int it = 0; it < 16; it++) {
            int col = it * 8 + wid;
            int n = n0 + col;
            #pragma unroll
            for (int rr = 0; rr < 4; rr++) {
                int r = rr * 32 + lane;
                float v = smf[r * 133 + col];
                if (EPI == 2) {
                    v += bias[n];
                    v = (v > 20.f) ? v : log1pf(__expf(v));
                }
                int m = m0 + r;
                int b = m >> 11, t = m & 2047;
                C[((long)(b * N + n)) * SEQL + t] = v;
            }
        }
        return;
    }

    #pragma unroll
    for (int it = 0; it < 16; it++) {
        int e = tid + (it << 8);
        int r = e >> 5, c4 = (e & 31) << 2;
        int n = n0 + c4;
        if (n < N) {
            float4 v = *(float4*)(smf + r * 132 + c4);
            if (EPI == 1) {
                v.x = v.x > 0.f ? v.x : 0.01f * v.x;
                v.y = v.y > 0.f ? v.y : 0.01f * v.y;
                v.z = v.z > 0.f ? v.z : 0.01f * v.z;
                v.w = v.w > 0.f ? v.w : 0.01f * v.w;
            } else if (EPI == 2) {
                v.x += bias[n];     v.y += bias[n + 1];
                v.z += bias[n + 2]; v.w += bias[n + 3];
                v.x = (v.x > 20.f) ? v.x : log1pf(__expf(v.x));
                v.y = (v.y > 20.f) ? v.y : log1pf(__expf(v.y));
                v.z = (v.z > 20.f) ? v.z : log1pf(__expf(v.z));
                v.w = (v.w > 20.f) ? v.w : log1pf(__expf(v.w));
            }
            long off = (long)(m0 + r) * N + n;
            *(float4*)(C + off) = v;
            if (SPLITC) {
                __half hx = __float2half_rn(v.x), hy = __float2half_rn(v.y);
                __half hz = __float2half_rn(v.z), hw = __float2half_rn(v.w);
                *(__half2*)(Ch + off)     = __halves2half2(hx, hy);
                *(__half2*)(Ch + off + 2) = __halves2half2(hz, hw);
                *(__half2*)(Cl + off)     = __halves2half2(
                    __float2half_rn(v.x - __half2float(hx)),
                    __float2half_rn(v.y - __half2float(hy)));
                *(__half2*)(Cl + off + 2) = __halves2half2(
                    __float2half_rn(v.z - __half2float(hz)),
                    __float2half_rn(v.w - __half2float(hw)));
            }
        }
    }
}

/* ---------------- 1. BatchNorm3d(eval) + LeakyReLU ---------------------- */
__global__ void bn_lrelu_k(const float* __restrict__ x, const float* __restrict__ g,
                           const float* __restrict__ be, const float* __restrict__ mu,
                           const float* __restrict__ var) {
    int i = blockIdx.x * 256 + threadIdx.x;
    if (i >= 2*DM*SEQL) return;
    int c = (i / SEQL) % DM;
    float v = (x[i] - mu[c]) * rsqrtf(var[c] + 1e-5f) * g[c] + be[c];
    g_act1[i] = v > 0.f ? v : 0.01f * v;
}

/* ------- 2. depthwise conv3d 3x3x3 SAME, fused transpose+split ---------- */
__global__ void dwconv_t(const float* __restrict__ wt) {
    __shared__ float s[32][33];
    int b = blockIdx.z, c0 = blockIdx.y * 32, t0 = blockIdx.x * 32;
    int tx = threadIdx.x, ty = threadIdx.y;     /* 32 x 8 */
    #pragma unroll
    for (int i = 0; i < 4; i++) {
        int c = c0 + ty + i*8;
        int t = t0 + tx;
        int w = t & 15, h = (t >> 4) & 15, d = t >> 8;
        const float* wp = wt + c * 27;
        const float* ip = g_act1 + (size_t)(b*DM + c) * SEQL;
        float acc = 0.f;
        #pragma unroll
        for (int kd = 0; kd < 3; kd++) {
            int dd = d + kd - 1; if (dd < 0 || dd > 7) continue;
            #pragma unroll
            for (int kh = 0; kh < 3; kh++) {
                int hh = h + kh - 1; if (hh < 0 || hh > 15) continue;
                #pragma unroll
                for (int kw = 0; kw < 3; kw++) {
                    int ww = w + kw - 1; if (ww < 0 || ww > 15) continue;
                    acc += wp[kd*9 + kh*3 + kw] * ip[dd*256 + hh*16 + ww];
                }
            }
        }
        s[ty + i*8][tx] = acc;
    }
    __syncthreads();
    #pragma unroll
    for (int i = 0; i < 4; i++) {
        int t = t0 + ty + i*8;
        int c = c0 + tx;
        float v = s[tx][ty + i*8];
        __half hv = __float2half_rn(v);
        long o = ((long)(b * SEQL + t)) * DM + c;
        g_Ah[o] = hv;
        g_Al[o] = __float2half_rn(v - __half2float(hv));
    }
}

/* -------- 32x32 transpose, fp32 in -> fp16 hi/lo out, dual-source ------- */
__global__ void transpose_h(const float* __restrict__ inf, const float* __restrict__ inb,
                            __half* __restrict__ hi, __half* __restrict__ lo,
                            int R, int Cc, int nb, long outBS) {
    __shared__ float s[32][33];
    int z = blockIdx.z;
    int dirb = z / nb, b = z - dirb * nb;
    const float* in = dirb ? inb : inf;
    hi += dirb * outBS; lo += dirb * outBS;
    int r0 = blockIdx.y * 32, c0 = blockIdx.x * 32;
    int tx = threadIdx.x, ty = threadIdx.y;     /* 32 x 8 */
    #pragma unroll
    for (int i = 0; i < 4; i++)
        s[ty + i*8][tx] = in[((long)(b * R + r0 + ty + i*8)) * Cc + c0 + tx];
    __syncthreads();
    #pragma unroll
    for (int i = 0; i < 4; i++) {
        float v = s[tx][ty + i*8];
        __half hv = __float2half_rn(v);
        long o = ((long)(b * Cc + c0 + ty + i*8)) * R + r0 + tx;
        hi[o] = hv;
        lo[o] = __float2half_rn(v - __half2float(hv));
    }
}

/* ---------------- 4. LayerNorm; emit X2 halves (orig + c-flip) ---------- */
__global__ void ln_k(const float* __restrict__ gam, const float* __restrict__ bet) {
    int m = blockIdx.x;
    __shared__ float red[16];
    const float* row = g_h2 + (size_t)m * DM;
    float s = 0.f, s2 = 0.f;
    for (int c = threadIdx.x; c < DM; c += 256) { float v = row[c]; s += v; s2 += v*v; }
    #pragma unroll
    for (int o = 16; o; o >>= 1) {
        s  += __shfl_xor_sync(~0u, s, o);
        s2 += __shfl_xor_sync(~0u, s2, o);
    }
    int wid = threadIdx.x >> 5, ln = threadIdx.x & 31;
    if (ln == 0) { red[wid] = s; red[8 + wid] = s2; }
    __syncthreads();
    float ts = 0.f, ts2 = 0.f;
    #pragma unroll
    for (int i = 0; i < 8; i++) { ts += red[i]; ts2 += red[8 + i]; }
    float mu = ts / 768.f;
    float var = ts2 / 768.f - mu * mu;
    float rs = rsqrtf(var + 1e-5f);
    for (int c = threadIdx.x; c < DM; c += 256) {
        float v = (row[c] - mu) * rs * gam[c] + bet[c];
        __half hv = __float2half_rn(v);
        __half lv = __float2half_rn(v - __half2float(hv));
        size_t o0 = (size_t)m * DM + c;
        size_t o1 = (size_t)(4096 + m) * DM + (DM - 1 - c);
        g_Ah[o0] = hv; g_Al[o0] = lv;
        g_Ah[o1] = hv; g_Al[o1] = lv;
    }
}

/* ---------------- 6. causal + anti-causal depthwise conv1d + SiLU ------- */
__global__ __launch_bounds__(256) void conv1d_k(const float* __restrict__ cw,
                                                const float* __restrict__ cb) {
    __shared__ float s[32][71];
    __shared__ float sw[32][4];
    __shared__ float sb[32];
    int b = blockIdx.z, d0 = blockIdx.y * 32, t0 = blockIdx.x * 64;
    int tid = threadIdx.x;
    if (tid < 128) sw[tid >> 2][tid & 3] = cw[(d0 + (tid >> 2)) * 4 + (tid & 3)];
    if (tid < 32)  sb[tid] = cb[d0 + tid];
    for (int e = tid; e < 32 * 70; e += 256) {
        int dd = e & 31, tt = e >> 5;
        int t = t0 - 3 + tt;
        float v = 0.f;
        if (t >= 0 && t < SEQL) v = g_xz[((size_t)(b * SEQL + t)) * (2*DI) + d0 + dd];
        s[dd][tt] = v;
    }
    __syncthreads();
    int tt = tid & 63, dg = tid >> 6;
    for (int dl = dg; dl < 32; dl += 4) {
        float w0 = sw[dl][0], w1 = sw[dl][1], w2 = sw[dl][2], w3 = sw[dl][3], bb = sb[dl];
        float f = w0*s[dl][tt]   + w1*s[dl][tt+1] + w2*s[dl][tt+2] + w3*s[dl][tt+3] + bb;
        float g = w0*s[dl][tt+6] + w1*s[dl][tt+5] + w2*s[dl][tt+4] + w3*s[dl][tt+3] + bb;
        size_t o = ((size_t)(b * DI + d0 + dl)) * SEQL + t0 + tt;
        g_xmf[o] = f / (1.f + __expf(-f));
        g_xmb[o] = g / (1.f + __expf(-g));
    }
}

/* ---------------- 10. selective scan (fwd + bwd) — frozen R10 body ------ */
__global__ __launch_bounds__(256) void scan_k(const float* __restrict__ A_log) {
    __shared__ float4 shbc[32][32];
    __shared__ float shred[8][32][32];
    int dir = blockIdx.z, b = blockIdx.y;
    int wid = threadIdx.x >> 5, lane = threadIdx.x & 31;
    int d = blockIdx.x * 8 + wid;
    const float* dt = g_dtt + (size_t)dir*NB*DI*SEQL + ((size_t)(b*DI + d)) * SEQL;
    const float* xm = (dir ? g_xmb : g_xmf) + ((size_t)(b*DI + d)) * SEQL;
    const float* xp = g_xp + (size_t)dir*MTOK*XPW + (size_t)b * SEQL * XPW;
    float* y = (dir ? g_yb : g_yf) + ((size_t)(b*DI + d)) * SEQL;
    const float L2E = 1.4426950408889634f;
    float A1 = -__expf(A_log[d*DS + lane])       * L2E;
    float A2 = -__expf(A_log[d*DS + 32 + lane])  * L2E;
    float h1 = 0.f, h2 = 0.f;
    for (int s0 = 0; s0 < SEQL; s0 += 32) {
        __syncthreads();
        for (int e = threadIdx.x; e < 1024; e += 256) {
            int r = e >> 5, n = e & 31;
            int t = dir ? (SEQL - 1 - (s0 + r)) : (s0 + r);
            const float* p = xp + (size_t)t * XPW;
            shbc[r][n] = make_float4(p[48 + n], p[80 + n], p[112 + n], p[144 + n]);
        }
        int tl = dir ? (SEQL - 1 - (s0 + lane)) : (s0 + lane);
        float dtv_b = dt[tl];
        float ux_b  = dtv_b * xm[tl];
        __syncthreads();
        #pragma unroll
        for (int j = 0; j < 32; j++) {
            float dtv = __shfl_sync(~0u, dtv_b, j);
            float uu  = __shfl_sync(~0u, ux_b, j);
            float4 bc = shbc[j][lane];
            float e1, e2;
            asm("ex2.approx.f32 %0, %1;" : "=f"(e1) : "f"(dtv * A1));
            asm("ex2.approx.f32 %0, %1;" : "=f"(e2) : "f"(dtv * A2));
            h1 = e1 * h1 + uu * bc.x;
            h2 = e2 * h2 + uu * bc.y;
            shred[wid][j][lane ^ j] = h1 * bc.z + h2 * bc.w;
        }
        __syncwarp();
        float sum = 0.f;
        #pragma unroll
        for (int i = 0; i < 32; i++) sum += shred[wid][lane][i ^ lane];
        y[dir ? (SEQL - 1 - s0 - lane) : (s0 + lane)] = sum;
    }
}

/* ---------------- 11. combine + gate -> u halves (token-major) ---------- */
__global__ void combine_k(const float* __restrict__ Dskip) {
    __shared__ float s[32][33];
    int b = blockIdx.z, d0 = blockIdx.y * 32, t0 = blockIdx.x * 32;
    int tx = threadIdx.x, ty = threadIdx.y;     /* 32 x 8 */
    #pragma unroll
    for (int i = 0; i < 4; i++) {
        int d = d0 + ty + i*8;
        size_t I = ((size_t)(b * DI + d)) * SEQL + t0 + tx;
        float v = g_yf[I] + g_yb[I] + Dskip[d] * (g_xmf[I] + g_xmb[I]);
        s[ty + i*8][tx] = v;
    }
    __syncthreads();
    #pragma unroll
    for (int i = 0; i < 4; i++) {
        int t = t0 + ty + i*8;
        int d = d0 + tx;
        float z = g_xz[((size_t)(b * SEQL + t)) * (2*DI) + DI + d];
        float sz = z / (1.f + __expf(-z));
        float u = s[tx][ty + i*8] * sz;
        __half hu = __float2half_rn(u);
        size_t o = ((size_t)(b * SEQL + t)) * DI + d;
        g_Ah[o] = hu;
        g_Al[o] = __float2half_rn(u - __half2float(hu));
    }
}

/* ---------------- 13. final: average 4 directions ----------------------- */
__global__ void final_k(float* __restrict__ out) {
    int i = blockIdx.x * 256 + threadIdx.x;
    if (i >= 2 * SEQL * DM) return;
    int c = i % DM;
    size_t ml = (size_t)(i / DM);
    out[i] = 0.25f * (g_v[ml * DM + c] +
                      g_v[(ml + (size_t)2 * SEQL) * DM + (DM - 1 - c)]);
}

/* ------------------------------------------------------------------------ */
extern "C" void kernel_launch(void* const* d_in, const int* in_sizes, int n_in,
                              void* d_out, int out_size) {
    const float* x        = (const float*)d_in[0];
    const float* bn_gamma = (const float*)d_in[1];
    const float* bn_beta  = (const float*)d_in[2];
    const float* bn_mean  = (const float*)d_in[3];
    const float* bn_var   = (const float*)d_in[4];
    const float* dw_w     = (const float*)d_in[5];
    const float* pw_w     = (const float*)d_in[6];
    const float* ln_gamma = (const float*)d_in[7];
    const float* ln_beta  = (const float*)d_in[8];
    const float* W_in     = (const float*)d_in[9];
    const float* conv_w   = (const float*)d_in[10];
    const float* conv_b   = (const float*)d_in[11];
    const float* W_x      = (const float*)d_in[12];
    const float* W_dt     = (const float*)d_in[13];
    const float* b_dt     = (const float*)d_in[14];
    const float* A_log    = (const float*)d_in[15];
    const float* D_skip   = (const float*)d_in[16];
    const float* W_out    = (const float*)d_in[17];
    float* out            = (float*)d_out;

    float *p_h2, *p_xz, *p_xmf, *p_xmb, *p_xp, *p_dtt, *p_v;
    __half *p_Ah, *p_Al, *p_Wh, *p_Wl, *p_xph, *p_xpl;
    cudaGetSymbolAddress((void**)&p_h2,   g_h2);
    cudaGetSymbolAddress((void**)&p_xz,   g_xz);
    cudaGetSymbolAddress((void**)&p_xmf,  g_xmf);
    cudaGetSymbolAddress((void**)&p_xmb,  g_xmb);
    cudaGetSymbolAddress((void**)&p_xp,   g_xp);
    cudaGetSymbolAddress((void**)&p_dtt,  g_dtt);
    cudaGetSymbolAddress((void**)&p_v,    g_v);
    cudaGetSymbolAddress((void**)&p_Ah,   g_Ah);
    cudaGetSymbolAddress((void**)&p_Al,   g_Al);
    cudaGetSymbolAddress((void**)&p_Wh,   g_Wh);
    cudaGetSymbolAddress((void**)&p_Wl,   g_Wl);
    cudaGetSymbolAddress((void**)&p_xph,  g_xph);
    cudaGetSymbolAddress((void**)&p_xpl,  g_xpl);

    cudaFuncSetAttribute(hmma_gemm_k<0,false,false>, cudaFuncAttributeMaxDynamicSharedMemorySize, SM_TOTAL);
    cudaFuncSetAttribute(hmma_gemm_k<0,true,false>,  cudaFuncAttributeMaxDynamicSharedMemorySize, SM_TOTAL);
    cudaFuncSetAttribute(hmma_gemm_k<1,false,false>, cudaFuncAttributeMaxDynamicSharedMemorySize, SM_TOTAL);
    cudaFuncSetAttribute(hmma_gemm_k<2,false,true>,  cudaFuncAttributeMaxDynamicSharedMemorySize, SM_TOTAL);

    /* [0] bn, [1] all weight splits (one launch), [2] dwconv, [3] pw GEMM */
    bn_lrelu_k<<<12288, 256>>>(x, bn_gamma, bn_beta, bn_mean, bn_var);
    split_all_k<<<(S_TOT + 255) / 256, 256>>>(pw_w, W_in, W_x, W_dt, W_out);
    dwconv_t<<<dim3(64, 24, 2), dim3(32, 8)>>>(dw_w);
    hmma_gemm_k<1,false,false><<<dim3(6, 32, 1), 256, SM_TOTAL>>>(
        p_Ah, p_Al, p_Wh + OFF_PW, p_Wl + OFF_PW, p_h2, nullptr, nullptr,
        nullptr, 4096, DM, DM, DM, 0L, 0L);
    /* layernorm -> X2 halves */
    ln_k<<<2*SEQL, 256>>>(ln_gamma, ln_beta);
    /* in_proj: [8192,768] x [3072,768]^T */
    hmma_gemm_k<0,false,false><<<dim3(24, 64, 1), 256, SM_TOTAL>>>(
        p_Ah, p_Al, p_Wh + OFF_IN, p_Wl + OFF_IN, p_xz, nullptr, nullptr,
        nullptr, MTOK, 2*DI, DM, DM, 0L, 0L);
    /* dual-direction conv1d + SiLU -> xm [b,d,t] */
    conv1d_k<<<dim3(32, 48, NB), 256>>>(conv_w, conv_b);
    /* xm (both dirs) -> token-major halves */
    transpose_h<<<dim3(64, 48, 8), dim3(32, 8)>>>(p_xmf, p_xmb, p_Ah, p_Al,
                                                  DI, SEQL, NB, (long)MTOK*DI);
    /* x_proj both dirs: [8192,1536] x [176,1536]^T (emits fp32 + halves) */
    hmma_gemm_k<0,true,false><<<dim3(2, 64, 2), 256, SM_TOTAL>>>(
        p_Ah, p_Al, p_Wh + OFF_X, p_Wl + OFF_X, p_xp, p_xph, p_xpl,
        nullptr, MTOK, XPW, DI, DI, (long)MTOK*DI, (long)MTOK*XPW);
    /* dt proj + softplus, transposed epilogue -> dtt [dir][b][d][t] */
    hmma_gemm_k<2,false,true><<<dim3(12, 64, 2), 256, SM_TOTAL>>>(
        p_xph, p_xpl, p_Wh + OFF_DT, p_Wl + OFF_DT, p_dtt, nullptr, nullptr,
        b_dt, MTOK, DI, DTR, XPW, (long)MTOK*XPW, (long)NB*DI*SEQL);
    /* selective scan */
    scan_k<<<dim3(DI/8, NB, 2), 256>>>(A_log);
    /* combine + gate -> u halves */
    combine_k<<<dim3(64, 48, NB), dim3(32, 8)>>>(D_skip);
    /* out_proj: [8192,1536] x [768,1536]^T */
    hmma_gemm_k<0,false,false><<<dim3(6, 64, 1), 256, SM_TOTAL>>>(
        p_Ah, p_Al, p_Wh + OFF_OUT, p_Wl + OFF_OUT, p_v, nullptr, nullptr,
        nullptr, MTOK, DM, DI, DI, 0L, 0L);
    final_k<<<12288, 256>>>(out);
    (void)in_sizes; (void)n_in; (void)out_size;
}

// round 17
// speedup vs baseline: 1.0728x; 1.0079x over previous
#include <cuda_runtime.h>
#include <cuda_fp16.h>
#include <mma.h>
#include <cstdint>
#include <cstdio>

using namespace nvcuda;

#define DM   768
#define DI   1536
#define DS   64
#define DTR  48
#define SEQL 2048
#define NB   4            /* effective batch: 2 orig x 2 channel-flip */
#define MTOK (NB*SEQL)    /* 8192 token rows */
#define XPW  176          /* DTR + 2*DS */

/* ---------------- scratch (static device globals; no allocation) -------- */
__device__ float g_act1[2*DM*SEQL];
__device__ float g_h2  [2*SEQL*DM];
__device__ float g_xz  [MTOK*2*DI];
__device__ float g_xmf [NB*DI*SEQL];
__device__ float g_xmb [NB*DI*SEQL];
__device__ float g_xp  [2*MTOK*XPW];        /* xp fp32: dir-f at 0, b at MTOK*XPW */
__device__ float g_dtt [2L*NB*DI*SEQL];     /* dt [dir][b][d][t] */
__device__ float g_yf  [NB*DI*SEQL];
__device__ float g_yb  [NB*DI*SEQL];
__device__ float g_v   [MTOK*DM];
/* fp16 hi/lo operand scratch */
__device__ __half g_Ah [2L*MTOK*DI];        /* A operand (2 dirs for x_proj) */
__device__ __half g_Al [2L*MTOK*DI];
__device__ __half g_Wh [4500000];
__device__ __half g_Wl [4500000];
__device__ __half g_xph[2*MTOK*XPW];
__device__ __half g_xpl[2*MTOK*XPW];

#define OFF_PW  0
#define OFF_IN  (DM*DM)
#define OFF_X   (OFF_IN + 2*DI*DM)
#define OFF_DT  (OFF_X + XPW*DI)
#define OFF_OUT (OFF_DT + DI*DTR)

/* segment sizes in float2 units */
#define S_PW  (DM*DM/2)
#define S_IN  (2*DI*DM/2)
#define S_X   (XPW*DI/2)
#define S_DT  (DI*DTR/2)
#define S_OUT (DM*DI/2)
#define S_TOT (S_PW+S_IN+S_X+S_DT+S_OUT)

/* ======================= small helpers ================================= */
__device__ __forceinline__ uint32_t smem_u32(const void* p) {
    uint32_t a;
    asm("{ .reg .u64 t; cvta.to.shared.u64 t, %1; cvt.u32.u64 %0, t; }" : "=r"(a) : "l"(p));
    return a;
}
__device__ __forceinline__ void cpa16(uint32_t dst, const void* src) {
    asm volatile("cp.async.cg.shared.global [%0], [%1], 16;\n" :: "r"(dst), "l"(src));
}
#define CP_COMMIT() asm volatile("cp.async.commit_group;\n" ::: "memory")
#define CP_WAIT(n)  asm volatile("cp.async.wait_group %0;\n" :: "n"(n) : "memory")

/* -------- fp32 -> (hi, lo) fp16 split: all 5 weights, one launch -------- */
__global__ void split_all_k(const float* __restrict__ pw, const float* __restrict__ win,
                            const float* __restrict__ wx, const float* __restrict__ wdt,
                            const float* __restrict__ wout) {
    int i = blockIdx.x * 256 + threadIdx.x;
    if (i >= S_TOT) return;
    const float* src; long dst;
    if (i < S_PW)                      { src = pw;   dst = OFF_PW/2  + i; }
    else if (i < S_PW+S_IN)            { src = win;  dst = OFF_IN/2  + (i - S_PW); i -= S_PW; }
    else if (i < S_PW+S_IN+S_X)        { src = wx;   dst = OFF_X/2   + (i - S_PW - S_IN); i -= S_PW+S_IN; }
    else if (i < S_PW+S_IN+S_X+S_DT)   { src = wdt;  dst = OFF_DT/2  + (i - S_PW - S_IN - S_X); i -= S_PW+S_IN+S_X; }
    else                               { src = wout; dst = OFF_OUT/2 + (i - S_PW - S_IN - S_X - S_DT); i -= S_PW+S_IN+S_X+S_DT; }
    float2 v = ((const float2*)src)[i];
    __half hx = __float2half_rn(v.x), hy = __float2half_rn(v.y);
    ((__half2*)g_Wh)[dst] = __halves2half2(hx, hy);
    ((__half2*)g_Wl)[dst] = __halves2half2(__float2half_rn(v.x - __half2float(hx)),
                                           __float2half_rn(v.y - __half2float(hy)));
}

/* ================= split-fp16 mma.sync GEMM ============================
   C[m,n] = sum_k A[m,k] * W[n,k],  A = Ah + Al, W = Wh + Wl (fp16 pairs).
   acc += Ah*Wh + Ah*Wl + Al*Wh  -> ~fp32 accuracy.  K-block = 48.        */
#define KBLK 48
#define HST 56                        /* smem row stride, halves (112 B) */
#define TILE_B (128*112)              /* 14336 B per 128xHST half tile */
#define SM_TOTAL (8*TILE_B)           /* 114688 bytes (2 stages x 4 arrays) */

typedef wmma::fragment<wmma::matrix_a,16,16,16,__half,wmma::row_major> HA;
typedef wmma::fragment<wmma::matrix_b,16,16,16,__half,wmma::col_major> HB;

template<int EPI, bool SPLITC, bool TRANSC>
__global__ __launch_bounds__(256, 2) void hmma_gemm_k(
    const __half* __restrict__ Ah_, const __half* __restrict__ Al_,
    const __half* __restrict__ Wh, const __half* __restrict__ Wl,
    float* __restrict__ C_, __half* __restrict__ Ch_, __half* __restrict__ Cl_,
    const float* __restrict__ bias, int M, int N, int K, int lda,
    long aBS, long cBS)
{
    extern __shared__ char smc[];
    float* smf = (float*)smc;
    int tid = threadIdx.x, wid = tid >> 5, lane = tid & 31;
    int m0 = blockIdx.y * 128, n0 = blockIdx.x * 128;
    int wm = (wid & 1) * 64, wn = (wid >> 1) * 32;
    uint32_t sbase = smem_u32(smc);
    const __half* Ah = Ah_ + blockIdx.z * aBS;
    const __half* Al = Al_ + blockIdx.z * aBS;
    float* C = C_ + blockIdx.z * cBS;
    __half* Ch = SPLITC ? Ch_ + blockIdx.z * cBS : nullptr;
    __half* Cl = SPLITC ? Cl_ + blockIdx.z * cBS : nullptr;

    wmma::fragment<wmma::accumulator,16,16,16,float> acc[4][2];
    #pragma unroll
    for (int i = 0; i < 4; i++)
        #pragma unroll
        for (int j = 0; j < 2; j++) wmma::fill_fragment(acc[i][j], 0.f);

    const int NKB = K / KBLK;

    /* 4 arrays x 128 rows x 6 float4-chunks = 3072 float4 per stage */
    auto prefetch = [&](int kb) {
        int k0 = kb * KBLK, s = kb & 1;
        int soff = s * (4 * TILE_B);
        #pragma unroll
        for (int i = 0; i < 12; i++) {
            int e = tid + (i << 8);
            int arr = e / 768, rem = e - arr * 768;
            int r = rem / 6, q = rem - r * 6;
            int off = soff + arr * TILE_B + r * 112 + q * 16;
            const __half* src;
            bool ok = true;
            if (arr < 2) {
                src = (arr == 0 ? Ah : Al) + (long)(m0 + r) * lda + k0 + q * 8;
            } else {
                src = (arr == 2 ? Wh : Wl) + (long)(n0 + r) * K + k0 + q * 8;
                ok = (n0 + r < N);
            }
            if (ok) cpa16(sbase + off, src);
            else    *(float4*)(smc + off) = make_float4(0.f, 0.f, 0.f, 0.f);
        }
        CP_COMMIT();
    };

    prefetch(0);
    for (int kb = 0; kb < NKB; kb++) {
        int s = kb & 1;
        CP_WAIT(0);
        __syncthreads();
        if (kb + 1 < NKB) prefetch(kb + 1);
        const char* st = smc + s * (4 * TILE_B);
        const __half* pAh = (const __half*)(st);
        const __half* pAl = (const __half*)(st + TILE_B);
        const __half* pBh = (const __half*)(st + 2*TILE_B);
        const __half* pBl = (const __half*)(st + 3*TILE_B);
        #pragma unroll
        for (int ks = 0; ks < 3; ks++) {
            HB bh[2], bl[2];
            #pragma unroll
            for (int j = 0; j < 2; j++) {
                wmma::load_matrix_sync(bh[j], pBh + (wn + j*16) * HST + ks*16, HST);
                wmma::load_matrix_sync(bl[j], pBl + (wn + j*16) * HST + ks*16, HST);
            }
            #pragma unroll
            for (int i = 0; i < 4; i++) {
                HA ah, al;
                wmma::load_matrix_sync(ah, pAh + (wm + i*16) * HST + ks*16, HST);
                wmma::load_matrix_sync(al, pAl + (wm + i*16) * HST + ks*16, HST);
                wmma::mma_sync(acc[i][0], ah, bh[0], acc[i][0]);
                wmma::mma_sync(acc[i][1], ah, bh[1], acc[i][1]);
                wmma::mma_sync(acc[i][0], ah, bl[0], acc[i][0]);
                wmma::mma_sync(acc[i][1], ah, bl[1], acc[i][1]);
                wmma::mma_sync(acc[i][0], al, bh[0], acc[i][0]);
                wmma::mma_sync(acc[i][1], al, bh[1], acc[i][1]);
            }
        }
    }
    __syncthreads();

    /* stage C through shared */
    constexpr int STGX = TRANSC ? 133 : 132;
    #pragma unroll
    for (int i = 0; i < 4; i++)
        #pragma unroll
        for (int j = 0; j < 2; j++)
            wmma::store_matrix_sync(smf + (wm + i*16) * STGX + wn + j*16,
                                    acc[i][j], STGX, wmma::mem_row_major);
    __syncthreads();

    if (TRANSC) {
        /* transposed output: out[(b*N + n)*SEQL + t],  m = b*SEQL + t */
        #pragma unroll
        for (int it = 0; it < 16; it++) {
            int col = it * 8 + wid;
            int n = n0 + col;
            #pragma unroll
            for (int rr = 0; rr < 4; rr++) {
                int r = rr * 32 + lane;
                float v = smf[r * 133 + col];
                if (EPI == 2) {
                    v += bias[n];
                    v = (v > 20.f) ? v : log1pf(__expf(v));
                }
                int m = m0 + r;
                int b = m >> 11, t = m & 2047;
                C[((long)(b * N + n)) * SEQL + t] = v;
            }
        }
        return;
    }

    #pragma unroll
    for (int it = 0; it < 16; it++) {
        int e = tid + (it << 8);
        int r = e >> 5, c4 = (e & 31) << 2;
        int n = n0 + c4;
        if (n < N) {
            float4 v = *(float4*)(smf + r * 132 + c4);
            if (EPI == 1) {
                v.x = v.x > 0.f ? v.x : 0.01f * v.x;
                v.y = v.y > 0.f ? v.y : 0.01f * v.y;
                v.z = v.z > 0.f ? v.z : 0.01f * v.z;
                v.w = v.w > 0.f ? v.w : 0.01f * v.w;
            } else if (EPI == 2) {
                v.x += bias[n];     v.y += bias[n + 1];
                v.z += bias[n + 2]; v.w += bias[n + 3];
                v.x = (v.x > 20.f) ? v.x : log1pf(__expf(v.x));
                v.y = (v.y > 20.f) ? v.y : log1pf(__expf(v.y));
                v.z = (v.z > 20.f) ? v.z : log1pf(__expf(v.z));
                v.w = (v.w > 20.f) ? v.w : log1pf(__expf(v.w));
            }
            long off = (long)(m0 + r) * N + n;
            *(float4*)(C + off) = v;
            if (SPLITC) {
                __half hx = __float2half_rn(v.x), hy = __float2half_rn(v.y);
                __half hz = __float2half_rn(v.z), hw = __float2half_rn(v.w);
                *(__half2*)(Ch + off)     = __halves2half2(hx, hy);
                *(__half2*)(Ch + off + 2) = __halves2half2(hz, hw);
                *(__half2*)(Cl + off)     = __halves2half2(
                    __float2half_rn(v.x - __half2float(hx)),
                    __float2half_rn(v.y - __half2float(hy)));
                *(__half2*)(Cl + off + 2) = __halves2half2(
                    __float2half_rn(v.z - __half2float(hz)),
                    __float2half_rn(v.w - __half2float(hw)));
            }
        }
    }
}

/* ---------------- 1. BatchNorm3d(eval) + LeakyReLU ---------------------- */
__global__ void bn_lrelu_k(const float* __restrict__ x, const float* __restrict__ g,
                           const float* __restrict__ be, const float* __restrict__ mu,
                           const float* __restrict__ var) {
    int i = blockIdx.x * 256 + threadIdx.x;
    if (i >= 2*DM*SEQL) return;
    int c = (i / SEQL) % DM;
    float v = (x[i] - mu[c]) * rsqrtf(var[c] + 1e-5f) * g[c] + be[c];
    g_act1[i] = v > 0.f ? v : 0.01f * v;
}

/* ------- 2. depthwise conv3d 3x3x3 SAME, fused transpose+split ---------- */
__global__ void dwconv_t(const float* __restrict__ wt) {
    __shared__ float s[32][33];
    int b = blockIdx.z, c0 = blockIdx.y * 32, t0 = blockIdx.x * 32;
    int tx = threadIdx.x, ty = threadIdx.y;     /* 32 x 8 */
    #pragma unroll
    for (int i = 0; i < 4; i++) {
        int c = c0 + ty + i*8;
        int t = t0 + tx;
        int w = t & 15, h = (t >> 4) & 15, d = t >> 8;
        const float* wp = wt + c * 27;
        const float* ip = g_act1 + (size_t)(b*DM + c) * SEQL;
        float acc = 0.f;
        #pragma unroll
        for (int kd = 0; kd < 3; kd++) {
            int dd = d + kd - 1; if (dd < 0 || dd > 7) continue;
            #pragma unroll
            for (int kh = 0; kh < 3; kh++) {
                int hh = h + kh - 1; if (hh < 0 || hh > 15) continue;
                #pragma unroll
                for (int kw = 0; kw < 3; kw++) {
                    int ww = w + kw - 1; if (ww < 0 || ww > 15) continue;
                    acc += wp[kd*9 + kh*3 + kw] * ip[dd*256 + hh*16 + ww];
                }
            }
        }
        s[ty + i*8][tx] = acc;
    }
    __syncthreads();
    #pragma unroll
    for (int i = 0; i < 4; i++) {
        int t = t0 + ty + i*8;
        int c = c0 + tx;
        float v = s[tx][ty + i*8];
        __half hv = __float2half_rn(v);
        long o = ((long)(b * SEQL + t)) * DM + c;
        g_Ah[o] = hv;
        g_Al[o] = __float2half_rn(v - __half2float(hv));
    }
}

/* -------- 32x32 transpose, fp32 in -> fp16 hi/lo out, dual-source ------- */
__global__ void transpose_h(const float* __restrict__ inf, const float* __restrict__ inb,
                            __half* __restrict__ hi, __half* __restrict__ lo,
                            int R, int Cc, int nb, long outBS) {
    __shared__ float s[32][33];
    int z = blockIdx.z;
    int dirb = z / nb, b = z - dirb * nb;
    const float* in = dirb ? inb : inf;
    hi += dirb * outBS; lo += dirb * outBS;
    int r0 = blockIdx.y * 32, c0 = blockIdx.x * 32;
    int tx = threadIdx.x, ty = threadIdx.y;     /* 32 x 8 */
    #pragma unroll
    for (int i = 0; i < 4; i++)
        s[ty + i*8][tx] = in[((long)(b * R + r0 + ty + i*8)) * Cc + c0 + tx];
    __syncthreads();
    #pragma unroll
    for (int i = 0; i < 4; i++) {
        float v = s[tx][ty + i*8];
        __half hv = __float2half_rn(v);
        long o = ((long)(b * Cc + c0 + ty + i*8)) * R + r0 + tx;
        hi[o] = hv;
        lo[o] = __float2half_rn(v - __half2float(hv));
    }
}

/* ---------------- 4. LayerNorm; emit X2 halves (orig + c-flip) ---------- */
__global__ void ln_k(const float* __restrict__ gam, const float* __restrict__ bet) {
    int m = blockIdx.x;
    __shared__ float red[16];
    const float* row = g_h2 + (size_t)m * DM;
    float s = 0.f, s2 = 0.f;
    for (int c = threadIdx.x; c < DM; c += 256) { float v = row[c]; s += v; s2 += v*v; }
    #pragma unroll
    for (int o = 16; o; o >>= 1) {
        s  += __shfl_xor_sync(~0u, s, o);
        s2 += __shfl_xor_sync(~0u, s2, o);
    }
    int wid = threadIdx.x >> 5, ln = threadIdx.x & 31;
    if (ln == 0) { red[wid] = s; red[8 + wid] = s2; }
    __syncthreads();
    float ts = 0.f, ts2 = 0.f;
    #pragma unroll
    for (int i = 0; i < 8; i++) { ts += red[i]; ts2 += red[8 + i]; }
    float mu = ts / 768.f;
    float var = ts2 / 768.f - mu * mu;
    float rs = rsqrtf(var + 1e-5f);
    for (int c = threadIdx.x; c < DM; c += 256) {
        float v = (row[c] - mu) * rs * gam[c] + bet[c];
        __half hv = __float2half_rn(v);
        __half lv = __float2half_rn(v - __half2float(hv));
        size_t o0 = (size_t)m * DM + c;
        size_t o1 = (size_t)(4096 + m) * DM + (DM - 1 - c);
        g_Ah[o0] = hv; g_Al[o0] = lv;
        g_Ah[o1] = hv; g_Al[o1] = lv;
    }
}

/* ---------------- 6. causal + anti-causal depthwise conv1d + SiLU ------- */
__global__ __launch_bounds__(256) void conv1d_k(const float* __restrict__ cw,
                                                const float* __restrict__ cb) {
    __shared__ float s[32][71];
    __shared__ float sw[32][4];
    __shared__ float sb[32];
    int b = blockIdx.z, d0 = blockIdx.y * 32, t0 = blockIdx.x * 64;
    int tid = threadIdx.x;
    if (tid < 128) sw[tid >> 2][tid & 3] = cw[(d0 + (tid >> 2)) * 4 + (tid & 3)];
    if (tid < 32)  sb[tid] = cb[d0 + tid];
    for (int e = tid; e < 32 * 70; e += 256) {
        int dd = e & 31, tt = e >> 5;
        int t = t0 - 3 + tt;
        float v = 0.f;
        if (t >= 0 && t < SEQL) v = g_xz[((size_t)(b * SEQL + t)) * (2*DI) + d0 + dd];
        s[dd][tt] = v;
    }
    __syncthreads();
    int tt = tid & 63, dg = tid >> 6;
    for (int dl = dg; dl < 32; dl += 4) {
        float w0 = sw[dl][0], w1 = sw[dl][1], w2 = sw[dl][2], w3 = sw[dl][3], bb = sb[dl];
        float f = w0*s[dl][tt]   + w1*s[dl][tt+1] + w2*s[dl][tt+2] + w3*s[dl][tt+3] + bb;
        float g = w0*s[dl][tt+6] + w1*s[dl][tt+5] + w2*s[dl][tt+4] + w3*s[dl][tt+3] + bb;
        size_t o = ((size_t)(b * DI + d0 + dl)) * SEQL + t0 + tt;
        g_xmf[o] = f / (1.f + __expf(-f));
        g_xmb[o] = g / (1.f + __expf(-g));
    }
}

/* ---------------- 10. selective scan (fwd + bwd) — frozen R10 body ------ */
__global__ __launch_bounds__(256) void scan_k(const float* __restrict__ A_log) {
    __shared__ float4 shbc[32][32];
    __shared__ float shred[8][32][32];
    int dir = blockIdx.z, b = blockIdx.y;
    int wid = threadIdx.x >> 5, lane = threadIdx.x & 31;
    int d = blockIdx.x * 8 + wid;
    const float* dt = g_dtt + (size_t)dir*NB*DI*SEQL + ((size_t)(b*DI + d)) * SEQL;
    const float* xm = (dir ? g_xmb : g_xmf) + ((size_t)(b*DI + d)) * SEQL;
    const float* xp = g_xp + (size_t)dir*MTOK*XPW + (size_t)b * SEQL * XPW;
    float* y = (dir ? g_yb : g_yf) + ((size_t)(b*DI + d)) * SEQL;
    const float L2E = 1.4426950408889634f;
    float A1 = -__expf(A_log[d*DS + lane])       * L2E;
    float A2 = -__expf(A_log[d*DS + 32 + lane])  * L2E;
    float h1 = 0.f, h2 = 0.f;
    for (int s0 = 0; s0 < SEQL; s0 += 32) {
        __syncthreads();
        for (int e = threadIdx.x; e < 1024; e += 256) {
            int r = e >> 5, n = e & 31;
            int t = dir ? (SEQL - 1 - (s0 + r)) : (s0 + r);
            const float* p = xp + (size_t)t * XPW;
            shbc[r][n] = make_float4(p[48 + n], p[80 + n], p[112 + n], p[144 + n]);
        }
        int tl = dir ? (SEQL - 1 - (s0 + lane)) : (s0 + lane);
        float dtv_b = dt[tl];
        float ux_b  = dtv_b * xm[tl];
        __syncthreads();
        #pragma unroll
        for (int j = 0; j < 32; j++) {
            float dtv = __shfl_sync(~0u, dtv_b, j);
            float uu  = __shfl_sync(~0u, ux_b, j);
            float4 bc = shbc[j][lane];
            float e1, e2;
            asm("ex2.approx.f32 %0, %1;" : "=f"(e1) : "f"(dtv * A1));
            asm("ex2.approx.f32 %0, %1;" : "=f"(e2) : "f"(dtv * A2));
            h1 = e1 * h1 + uu * bc.x;
            h2 = e2 * h2 + uu * bc.y;
            shred[wid][j][lane ^ j] = h1 * bc.z + h2 * bc.w;
        }
        __syncwarp();
        float sum = 0.f;
        #pragma unroll
        for (int i = 0; i < 32; i++) sum += shred[wid][lane][i ^ lane];
        y[dir ? (SEQL - 1 - s0 - lane) : (s0 + lane)] = sum;
    }
}

/* ---------------- 11. combine + gate -> u halves (token-major) ---------- */
__global__ void combine_k(const float* __restrict__ Dskip) {
    __shared__ float s[32][33];
    int b = blockIdx.z, d0 = blockIdx.y * 32, t0 = blockIdx.x * 32;
    int tx = threadIdx.x, ty = threadIdx.y;     /* 32 x 8 */
    #pragma unroll
    for (int i = 0; i < 4; i++) {
        int d = d0 + ty + i*8;
        size_t I = ((size_t)(b * DI + d)) * SEQL + t0 + tx;
        float v = g_yf[I] + g_yb[I] + Dskip[d] * (g_xmf[I] + g_xmb[I]);
        s[ty + i*8][tx] = v;
    }
    __syncthreads();
    #pragma unroll
    for (int i = 0; i < 4; i++) {
        int t = t0 + ty + i*8;
        int d = d0 + tx;
        float z = g_xz[((size_t)(b * SEQL + t)) * (2*DI) + DI + d];
        float sz = z / (1.f + __expf(-z));
        float u = s[tx][ty + i*8] * sz;
        __half hu = __float2half_rn(u);
        size_t o = ((size_t)(b * SEQL + t)) * DI + d;
        g_Ah[o] = hu;
        g_Al[o] = __float2half_rn(u - __half2float(hu));
    }
}

/* ---------------- 13. final: average 4 directions ----------------------- */
__global__ void final_k(float* __restrict__ out) {
    int i = blockIdx.x * 256 + threadIdx.x;
    if (i >= 2 * SEQL * DM) return;
    int c = i % DM;
    size_t ml = (size_t)(i / DM);
    out[i] = 0.25f * (g_v[ml * DM + c] +
                      g_v[(ml + (size_t)2 * SEQL) * DM + (DM - 1 - c)]);
}

/* ------------------------------------------------------------------------ */
extern "C" void kernel_launch(void* const* d_in, const int* in_sizes, int n_in,
                              void* d_out, int out_size) {
    const float* x        = (const float*)d_in[0];
    const float* bn_gamma = (const float*)d_in[1];
    const float* bn_beta  = (const float*)d_in[2];
    const float* bn_mean  = (const float*)d_in[3];
    const float* bn_var   = (const float*)d_in[4];
    const float* dw_w     = (const float*)d_in[5];
    const float* pw_w     = (const float*)d_in[6];
    const float* ln_gamma = (const float*)d_in[7];
    const float* ln_beta  = (const float*)d_in[8];
    const float* W_in     = (const float*)d_in[9];
    const float* conv_w   = (const float*)d_in[10];
    const float* conv_b   = (const float*)d_in[11];
    const float* W_x      = (const float*)d_in[12];
    const float* W_dt     = (const float*)d_in[13];
    const float* b_dt     = (const float*)d_in[14];
    const float* A_log    = (const float*)d_in[15];
    const float* D_skip   = (const float*)d_in[16];
    const float* W_out    = (const float*)d_in[17];
    float* out            = (float*)d_out;

    float *p_h2, *p_xz, *p_xmf, *p_xmb, *p_xp, *p_dtt, *p_v;
    __half *p_Ah, *p_Al, *p_Wh, *p_Wl, *p_xph, *p_xpl;
    cudaGetSymbolAddress((void**)&p_h2,   g_h2);
    cudaGetSymbolAddress((void**)&p_xz,   g_xz);
    cudaGetSymbolAddress((void**)&p_xmf,  g_xmf);
    cudaGetSymbolAddress((void**)&p_xmb,  g_xmb);
    cudaGetSymbolAddress((void**)&p_xp,   g_xp);
    cudaGetSymbolAddress((void**)&p_dtt,  g_dtt);
    cudaGetSymbolAddress((void**)&p_v,    g_v);
    cudaGetSymbolAddress((void**)&p_Ah,   g_Ah);
    cudaGetSymbolAddress((void**)&p_Al,   g_Al);
    cudaGetSymbolAddress((void**)&p_Wh,   g_Wh);
    cudaGetSymbolAddress((void**)&p_Wl,   g_Wl);
    cudaGetSymbolAddress((void**)&p_xph,  g_xph);
    cudaGetSymbolAddress((void**)&p_xpl,  g_xpl);

    cudaFuncSetAttribute(hmma_gemm_k<0,false,false>, cudaFuncAttributeMaxDynamicSharedMemorySize, SM_TOTAL);
    cudaFuncSetAttribute(hmma_gemm_k<0,true,false>,  cudaFuncAttributeMaxDynamicSharedMemorySize, SM_TOTAL);
    cudaFuncSetAttribute(hmma_gemm_k<1,false,false>, cudaFuncAttributeMaxDynamicSharedMemorySize, SM_TOTAL);
    cudaFuncSetAttribute(hmma_gemm_k<2,false,true>,  cudaFuncAttributeMaxDynamicSharedMemorySize, SM_TOTAL);

    /* [0] bn, [1] all weight splits (one launch), [2] dwconv, [3] pw GEMM */
    bn_lrelu_k<<<12288, 256>>>(x, bn_gamma, bn_beta, bn_mean, bn_var);
    split_all_k<<<(S_TOT + 255) / 256, 256>>>(pw_w, W_in, W_x, W_dt, W_out);
    dwconv_t<<<dim3(64, 24, 2), dim3(32, 8)>>>(dw_w);
    hmma_gemm_k<1,false,false><<<dim3(6, 32, 1), 256, SM_TOTAL>>>(
        p_Ah, p_Al, p_Wh + OFF_PW, p_Wl + OFF_PW, p_h2, nullptr, nullptr,
        nullptr, 4096, DM, DM, DM, 0L, 0L);
    /* layernorm -> X2 halves */
    ln_k<<<2*SEQL, 256>>>(ln_gamma, ln_beta);
    /* in_proj: [8192,768] x [3072,768]^T */
    hmma_gemm_k<0,false,false><<<dim3(24, 64, 1), 256, SM_TOTAL>>>(
        p_Ah, p_Al, p_Wh + OFF_IN, p_Wl + OFF_IN, p_xz, nullptr, nullptr,
        nullptr, MTOK, 2*DI, DM, DM, 0L, 0L);
    /* dual-direction conv1d + SiLU -> xm [b,d,t] */
    conv1d_k<<<dim3(32, 48, NB), 256>>>(conv_w, conv_b);
    /* xm (both dirs) -> token-major halves */
    transpose_h<<<dim3(64, 48, 8), dim3(32, 8)>>>(p_xmf, p_xmb, p_Ah, p_Al,
                                                  DI, SEQL, NB, (long)MTOK*DI);
    /* x_proj both dirs: [8192,1536] x [176,1536]^T (emits fp32 + halves) */
    hmma_gemm_k<0,true,false><<<dim3(2, 64, 2), 256, SM_TOTAL>>>(
        p_Ah, p_Al, p_Wh + OFF_X, p_Wl + OFF_X, p_xp, p_xph, p_xpl,
        nullptr, MTOK, XPW, DI, DI, (long)MTOK*DI, (long)MTOK*XPW);
    /* dt proj + softplus, transposed epilogue -> dtt [dir][b][d][t] */
    hmma_gemm_k<2,false,true><<<dim3(12, 64, 2), 256, SM_TOTAL>>>(
        p_xph, p_xpl, p_Wh + OFF_DT, p_Wl + OFF_DT, p_dtt, nullptr, nullptr,
        b_dt, MTOK, DI, DTR, XPW, (long)MTOK*XPW, (long)NB*DI*SEQL);
    /* selective scan */
    scan_k<<<dim3(DI/8, NB, 2), 256>>>(A_log);
    /* combine + gate -> u halves */
    combine_k<<<dim3(64, 48, NB), dim3(32, 8)>>>(D_skip);
    /* out_proj: [8192,1536] x [768,1536]^T */
    hmma_gemm_k<0,false,false><<<dim3(6, 64, 1), 256, SM_TOTAL>>>(
        p_Ah, p_Al, p_Wh + OFF_OUT, p_Wl + OFF_OUT, p_v, nullptr, nullptr,
        nullptr, MTOK, DM, DI, DI, 0L, 0L);
    final_k<<<12288, 256>>>(out);
    (void)in_sizes; (void)n_in; (void)out_size;
}